// round 14
// baseline (speedup 1.0000x reference)
#include <cuda_runtime.h>
#include <cuda_fp16.h>
#include <cstdint>

// ===========================================================================
// ChebyKANLinear, mma.sync m16n8k16 FP16 (fp32 accumulate).
// R13: 16 consumer warps (4/SMSP, warp tile 32x64) + 2 producer warps,
// 576 threads. Tests whether the 11.3cyc/HMMA spacing is per-warp
// dependent-issue (expect ~2x) or hardware pipe rate (expect no change).
// Ring/barrier protocol = R11; producer = R12; prep = R12 (coalesced).
// ===========================================================================

#define BATCH   8192
#define IN_F    1024
#define OUT_F   1024
#define BM      128
#define BN      256
#define KC      64            // 8 i-values * 8 degrees per chunk
#define NCHUNK  128           // IN_F / 8
#define A_BYTES 16384         // BM * KC * 2 (fp16)
#define B_BYTES 32768         // BN * KC * 2 (fp16)
#define STAGE_BYTES (A_BYTES + B_BYTES)
#define NSTG    4
#define NTHR    576
#define CSCALE  4096.0f
#define OSCALE  (1.0f / 4096.0f)

// Static device scratch (no runtime allocation allowed)
__device__ uint32_t g_BF[(size_t)128 * 16 * 2048];    // B fp16 frags, 16 MB
__device__ float g_part[512 * OUT_F];                 // bias partials, 2 MB
__device__ float g_bias[OUT_F];

// ---------------------------------------------------------------- utils
__device__ __forceinline__ uint32_t h2pack(float lo, float hi) {
    __half2 h = __floats2half2_rn(lo, hi);
    return *reinterpret_cast<uint32_t*>(&h);
}

__device__ __forceinline__ float fast_tanh(float x) {
    float e = __expf(2.f * x);
    return 1.f - __fdividef(2.f, e + 1.f);
}

__device__ __forceinline__ void cpa16(uint32_t dst, const void* src) {
    asm volatile("cp.async.cg.shared.global [%0], [%1], 16;\n" :: "r"(dst), "l"(src));
}
__device__ __forceinline__ void cpa_commit() { asm volatile("cp.async.commit_group;\n"); }
template <int N>
__device__ __forceinline__ void cpa_wait() {
    asm volatile("cp.async.wait_group %0;\n" :: "n"(N) : "memory");
}

// Split named barriers, 576 participants each.
// FULL[s]: id 1+s (stage s data ready). FREE[s]: id 5+s (stage s reusable).
__device__ __forceinline__ void bar_sync_id(int id) {
    asm volatile("bar.sync %0, %1;" :: "r"(id), "n"(NTHR) : "memory");
}
__device__ __forceinline__ void bar_arrive_id(int id) {
    asm volatile("bar.arrive %0, %1;" :: "r"(id), "n"(NTHR) : "memory");
}

__device__ __forceinline__ void lds128(uint4& v, uint32_t addr) {
    asm volatile("ld.shared.v4.b32 {%0,%1,%2,%3}, [%4];"
                 : "=r"(v.x), "=r"(v.y), "=r"(v.z), "=r"(v.w) : "r"(addr));
}
__device__ __forceinline__ void sts128(uint32_t addr, uint32_t a, uint32_t b,
                                       uint32_t c, uint32_t d) {
    asm volatile("st.shared.v4.b32 [%0], {%1,%2,%3,%4};"
                 :: "r"(addr), "r"(a), "r"(b), "r"(c), "r"(d));
}

__device__ __forceinline__ void mma16(float* c, const uint4& a, uint32_t b0, uint32_t b1) {
    asm volatile(
        "mma.sync.aligned.m16n8k16.row.col.f32.f16.f16.f32 "
        "{%0,%1,%2,%3},{%4,%5,%6,%7},{%8,%9},{%0,%1,%2,%3};\n"
        : "+f"(c[0]), "+f"(c[1]), "+f"(c[2]), "+f"(c[3])
        : "r"(a.x), "r"(a.y), "r"(a.z), "r"(a.w), "r"(b0), "r"(b1));
}

// A-fragment lane swizzle (conflict-free for gen STS.128 and consumer LDS.128)
__device__ __forceinline__ uint32_t a_lswz(uint32_t lane_c) {
    return (lane_c * 16u) ^ (((lane_c >> 3) & 3u) << 4);
}

// ---------------------------------------------------------------- prologues
// B fragments (fp16, scaled by 2^12) + per-block bias partials.
// Block b handles i-pair (i0, i0+1), i0 = (b>>2)*8 + (b&3)*2.
// Coalesced: coef rows staged into smem with float4 loads first.
__global__ void __launch_bounds__(256) prep_kernel(const float* __restrict__ coef) {
    extern __shared__ float sbuf[];                    // 72KB rows + 32KB stg
    float* rows = sbuf;                                // [2][9216]
    uint32_t* stg = reinterpret_cast<uint32_t*>(sbuf + 18432);
    const int b = blockIdx.x;
    const int c = b >> 2, s = b & 3;
    const int i0 = c * 8 + s * 2;
    {
        const float4* src4 = reinterpret_cast<const float4*>(coef + (size_t)i0 * 9216);
        float4* dst4 = reinterpret_cast<float4*>(rows);
        #pragma unroll
        for (int k = 0; k < 18; k++)
            dst4[threadIdx.x + (k << 8)] = src4[threadIdx.x + (k << 8)];
    }
    __syncthreads();
    #pragma unroll
    for (int r = 0; r < 4; r++) {
        const int col = threadIdx.x + (r << 8);
        const float* cv0 = rows + col * 9;             // stride 9 coprime 32: no conflicts
        const float* cv1 = rows + 9216 + col * 9;
        const int g = col & 7, colpar = (col >> 3) & 1;
        const int nip = (col >> 4) & 3, wnG = col >> 6;
        const int base = wnG * 512 + nip * 128 + colpar * 2;
        #pragma unroll
        for (int t = 0; t < 4; t++) {
            stg[base + (g * 4 + t) * 4 + 0] =
                h2pack(cv0[2 * t + 1] * CSCALE, cv0[2 * t + 2] * CSCALE);
            stg[base + (g * 4 + t) * 4 + 1] =
                h2pack(cv1[2 * t + 1] * CSCALE, cv1[2 * t + 2] * CSCALE);
        }
        g_part[(size_t)b * OUT_F + col] = cv0[0] + cv1[0];   // bias partial
    }
    __syncthreads();
    float4* dst = reinterpret_cast<float4*>(g_BF);
    const float4* src = reinterpret_cast<const float4*>(stg);
    #pragma unroll
    for (int k = 0; k < 8; k++) {
        const int q = threadIdx.x + (k << 8);   // 0..2047
        const int wnG = q >> 7, inner = q & 127;
        dst[(size_t)(c * 16 + wnG) * 512 + s * 128 + inner] = src[q];
    }
}

// bias[o] = sum over 512 partials (deterministic fixed order)
__global__ void __launch_bounds__(256) bias_red_kernel() {
    const int o = (blockIdx.x << 8) + threadIdx.x;
    float s0 = 0.f, s1 = 0.f, s2 = 0.f, s3 = 0.f;
    #pragma unroll 4
    for (int b = 0; b < 512; b += 4) {
        s0 += g_part[(size_t)(b + 0) * OUT_F + o];
        s1 += g_part[(size_t)(b + 1) * OUT_F + o];
        s2 += g_part[(size_t)(b + 2) * OUT_F + o];
        s3 += g_part[(size_t)(b + 3) * OUT_F + o];
    }
    g_bias[o] = (s0 + s1) + (s2 + s3);
}

// ---------------------------------------------------------------- main GEMM
// 576 thr: warps 0-15 consumers (warp tile 32x64: wm=w>>2 row-block, wn=w&3
// col-block), warps 16-17 producers. 4-stage ring = 192KB smem.
__global__ void __launch_bounds__(NTHR, 1) cheby_main(const float* __restrict__ X,
                                                      float* __restrict__ Out) {
    extern __shared__ uint8_t sm[];
    const uint32_t smA = (uint32_t)__cvta_generic_to_shared(sm);          // 4 x 16KB
    const uint32_t smB = smA + NSTG * A_BYTES;                            // 4 x 32KB

    const int tid  = threadIdx.x;
    const int lane = tid & 31;
    const int w    = tid >> 5;
    const int bm   = blockIdx.y << 7;
    const int bx   = blockIdx.x;
    const int bn   = bx << 8;

    const float4* bsrc = reinterpret_cast<const float4*>(g_BF);

    if (w < 16) {
        // ======================= CONSUMER (512 threads) =====================
        const int wm = w >> 2;           // 0..3 (32-row block)
        const int wn = w & 3;            // 0..3 (64-col block)
        const int g  = lane >> 2;
        const int t  = lane & 3;
        const uint32_t lsw = a_lswz((uint32_t)lane);

        float acc[2][8][4];
        #pragma unroll
        for (int mi = 0; mi < 2; mi++)
            #pragma unroll
            for (int ni = 0; ni < 8; ni++)
                #pragma unroll
                for (int q = 0; q < 4; q++) acc[mi][ni][q] = 0.f;

        for (int c = 0; c < NCHUNK; c++) {
            const int st = c & 3;
            bar_sync_id(1 + st);                 // wait stage FULL
            // A: [s:4][G:8][512B]; warp rows: G = wm*2 + mi
            const uint32_t aBase = smA + (uint32_t)(st * A_BYTES + wm * 1024) + lsw;
            const uint32_t bBase = smB + (uint32_t)(st * B_BYTES + wn * 8192 + lane * 16);

            #pragma unroll
            for (int s = 0; s < 4; s++) {
                uint4 aC[2];
                #pragma unroll
                for (int mi = 0; mi < 2; mi++)
                    lds128(aC[mi], aBase + (uint32_t)(s * 4096 + mi * 512));
                uint4 bC[4];
                #pragma unroll
                for (int nip = 0; nip < 4; nip++)
                    lds128(bC[nip], bBase + (uint32_t)(s * 2048 + nip * 512));
                #pragma unroll
                for (int ni = 0; ni < 8; ni++) {
                    const uint32_t b0 = (ni & 1) ? bC[ni >> 1].z : bC[ni >> 1].x;
                    const uint32_t b1 = (ni & 1) ? bC[ni >> 1].w : bC[ni >> 1].y;
                    #pragma unroll
                    for (int mi = 0; mi < 2; mi++)
                        mma16(acc[mi][ni], aC[mi], b0, b1);
                }
            }
            bar_arrive_id(5 + st);               // stage FREE
        }

        // --- epilogue: out = acc * 2^-12 + bias ---
        #pragma unroll
        for (int ni = 0; ni < 8; ni++) {
            const int cc = bn + (wn << 6) + (ni << 3) + (t << 1);
            const float2 bv = *reinterpret_cast<const float2*>(g_bias + cc);
            #pragma unroll
            for (int mi = 0; mi < 2; mi++) {
                const int r0 = bm + (wm << 5) + (mi << 4) + g;
                float2 o0 = { fmaf(acc[mi][ni][0], OSCALE, bv.x),
                              fmaf(acc[mi][ni][1], OSCALE, bv.y) };
                float2 o1 = { fmaf(acc[mi][ni][2], OSCALE, bv.x),
                              fmaf(acc[mi][ni][3], OSCALE, bv.y) };
                *reinterpret_cast<float2*>(Out + (size_t)r0 * OUT_F + cc)       = o0;
                *reinterpret_cast<float2*>(Out + (size_t)(r0 + 8) * OUT_F + cc) = o1;
            }
        }
    } else {
        // ======================= PRODUCER (64 threads) ======================
        const int ptid = tid - 512;              // 0..63
        // 4 generator units per thread: u = ptid + e*64, u in [0,256)
        // unit u: s = u&3, g = (u>>2)&7, G = u>>5; rows G*16+g, +8; i = 8c+2s,+1

        #define PRODUCE(n)                                                        \
        do {                                                                      \
            const int st_ = (n) & 3;                                              \
            /* B: 4 wnG blocks of 512 float4; 32 cpa16 per thread */              \
            const uint32_t dstB_ = smB + (uint32_t)(st_ * B_BYTES);               \
            _Pragma("unroll")                                                     \
            for (int k = 0; k < 32; k++) {                                        \
                const int wng = k >> 3;                                           \
                const int inner = ptid + ((k & 7) << 6);                          \
                cpa16(dstB_ + (uint32_t)(wng * 8192 + inner * 16),                \
                      bsrc + (size_t)((n) * 16 + (bx << 2) + wng) * 512 + inner); \
            }                                                                     \
            cpa_commit();                                                         \
            /* A generation with fused tanh */                                    \
            const uint32_t aDst_ = smA + (uint32_t)(st_ * A_BYTES);               \
            _Pragma("unroll")                                                     \
            for (int e = 0; e < 4; e++) {                                         \
                const int u = ptid + (e << 6);                                    \
                const int s_ = u & 3, g_ = (u >> 2) & 7, G_ = u >> 5;             \
                const int rA = bm + (G_ << 4) + g_;                               \
                const float2 xA = *reinterpret_cast<const float2*>(               \
                    X + (size_t)rA * IN_F + ((n) << 3) + (s_ << 1));              \
                const float2 xB = *reinterpret_cast<const float2*>(               \
                    X + (size_t)(rA + 8) * IN_F + ((n) << 3) + (s_ << 1));        \
                const float tA0 = fast_tanh(xA.x), tA1 = fast_tanh(xA.y);         \
                const float tB0 = fast_tanh(xB.x), tB1 = fast_tanh(xB.y);         \
                float TA0[8], TA1[8], TB0[8], TB1[8];                             \
                TA0[0] = tA0; TA1[0] = tA1; TB0[0] = tB0; TB1[0] = tB1;           \
                TA0[1] = 2.f * tA0 * tA0 - 1.f;                                   \
                TA1[1] = 2.f * tA1 * tA1 - 1.f;                                   \
                TB0[1] = 2.f * tB0 * tB0 - 1.f;                                   \
                TB1[1] = 2.f * tB1 * tB1 - 1.f;                                   \
                _Pragma("unroll")                                                 \
                for (int d = 2; d < 8; d++) {                                     \
                    TA0[d] = 2.f * tA0 * TA0[d - 1] - TA0[d - 2];                 \
                    TA1[d] = 2.f * tA1 * TA1[d - 1] - TA1[d - 2];                 \
                    TB0[d] = 2.f * tB0 * TB0[d - 1] - TB0[d - 2];                 \
                    TB1[d] = 2.f * tB1 * TB1[d - 1] - TB1[d - 2];                 \
                }                                                                 \
                const uint32_t ab_ = aDst_ + (uint32_t)(s_ * 4096 + G_ * 512);    \
                _Pragma("unroll")                                                 \
                for (int t = 0; t < 4; t++)                                       \
                    sts128(ab_ + a_lswz((uint32_t)(g_ * 4 + t)),                  \
                           h2pack(TA0[2 * t], TA0[2 * t + 1]),                    \
                           h2pack(TB0[2 * t], TB0[2 * t + 1]),                    \
                           h2pack(TA1[2 * t], TA1[2 * t + 1]),                    \
                           h2pack(TB1[2 * t], TB1[2 * t + 1]));                   \
            }                                                                     \
        } while (0)

        // n=0: no FREE wait, no arrive yet
        PRODUCE(0);
        for (int n = 1; n < NCHUNK; n++) {
            if (n >= NSTG) bar_sync_id(5 + (n & 3));   // wait stage FREE
            PRODUCE(n);
            cpa_wait<1>();                              // group n-1 drained
            bar_arrive_id(1 + ((n - 1) & 3));           // stage n-1 FULL
        }
        cpa_wait<0>();                                  // last group drained
        bar_arrive_id(1 + ((NCHUNK - 1) & 3));          // last stage FULL
        #undef PRODUCE
    }
}

// --------------------------------------------------------------------------
extern "C" void kernel_launch(void* const* d_in, const int* in_sizes, int n_in,
                              void* d_out, int out_size) {
    (void)in_sizes; (void)n_in; (void)out_size;
    const float* x    = (const float*)d_in[0];
    const float* coef = (const float*)d_in[1];
    float* out        = (float*)d_out;

    const int smem_bytes = NSTG * STAGE_BYTES;   // 196608
    cudaFuncSetAttribute(cheby_main, cudaFuncAttributeMaxDynamicSharedMemorySize,
                         smem_bytes);
    const int prep_smem = 18432 * 4 + 8192 * 4;  // 106496
    cudaFuncSetAttribute(prep_kernel, cudaFuncAttributeMaxDynamicSharedMemorySize,
                         prep_smem);

    prep_kernel<<<512, 256, prep_smem>>>(coef);
    bias_red_kernel<<<4, 256>>>();
    cheby_main<<<dim3(OUT_F / BN, BATCH / BM), NTHR, smem_bytes>>>(x, out);
}

// round 15
// speedup vs baseline: 1.0157x; 1.0157x over previous
#include <cuda_runtime.h>
#include <cuda_fp16.h>
#include <cstdint>

// ===========================================================================
// ChebyKANLinear, mma.sync m16n8k16 FP16 (fp32 accumulate).
// R14: K-split load balancing. 1024 units (64 bm x 4 bn x 4 kq, K=2048 each)
// -> ceil(1024/148)=7 units/SM = 98.8% wave balance (vs 2-tile 86.5%).
// Units write fp32 partials; last-arriving CTA per tile (ticket atomics,
// fixed kq summation order) reduces + bias + scale -> Out. Mainloop, ring,
// split named barriers, producer, prep identical to the proven R11/R13 code.
// ===========================================================================

#define BATCH   8192
#define IN_F    1024
#define OUT_F   1024
#define BM      128
#define BN      256
#define KC      64            // 8 i-values * 8 degrees per chunk
#define NCHUNK  32            // 2048 K per unit / 64
#define A_BYTES 16384         // BM * KC * 2 (fp16)
#define B_BYTES 32768         // BN * KC * 2 (fp16)
#define STAGE_BYTES (A_BYTES + B_BYTES)
#define NSTG    4
#define NTHR    384
#define CSCALE  4096.0f
#define OSCALE  (1.0f / 4096.0f)

// Static device scratch (no runtime allocation allowed)
__device__ uint32_t g_BF[(size_t)128 * 16 * 2048];    // B fp16 frags, 16 MB
__device__ float g_Pt[(size_t)1024 * 32768];          // K-split partials, 128 MB
__device__ float g_part[512 * OUT_F];                 // bias partials, 2 MB
__device__ float g_bias[OUT_F];
__device__ int   g_tk[256];                           // per-tile tickets (0-init)

// ---------------------------------------------------------------- utils
__device__ __forceinline__ uint32_t h2pack(float lo, float hi) {
    __half2 h = __floats2half2_rn(lo, hi);
    return *reinterpret_cast<uint32_t*>(&h);
}

__device__ __forceinline__ float fast_tanh(float x) {
    float e = __expf(2.f * x);
    return 1.f - __fdividef(2.f, e + 1.f);
}

__device__ __forceinline__ void cpa16(uint32_t dst, const void* src) {
    asm volatile("cp.async.cg.shared.global [%0], [%1], 16;\n" :: "r"(dst), "l"(src));
}
__device__ __forceinline__ void cpa_commit() { asm volatile("cp.async.commit_group;\n"); }
template <int N>
__device__ __forceinline__ void cpa_wait() {
    asm volatile("cp.async.wait_group %0;\n" :: "n"(N) : "memory");
}

// Split named barriers (384 participants): FULL[s]=1+s, FREE[s]=5+s.
// Barrier 10 (256 participants): consumer-only epilogue rendezvous.
__device__ __forceinline__ void bar_sync_id(int id) {
    asm volatile("bar.sync %0, %1;" :: "r"(id), "n"(NTHR) : "memory");
}
__device__ __forceinline__ void bar_arrive_id(int id) {
    asm volatile("bar.arrive %0, %1;" :: "r"(id), "n"(NTHR) : "memory");
}
__device__ __forceinline__ void bar_sync_cons() {
    asm volatile("bar.sync 10, 256;" ::: "memory");
}

__device__ __forceinline__ void lds128(uint4& v, uint32_t addr) {
    asm volatile("ld.shared.v4.b32 {%0,%1,%2,%3}, [%4];"
                 : "=r"(v.x), "=r"(v.y), "=r"(v.z), "=r"(v.w) : "r"(addr));
}
__device__ __forceinline__ void sts128(uint32_t addr, uint32_t a, uint32_t b,
                                       uint32_t c, uint32_t d) {
    asm volatile("st.shared.v4.b32 [%0], {%1,%2,%3,%4};"
                 :: "r"(addr), "r"(a), "r"(b), "r"(c), "r"(d));
}

__device__ __forceinline__ void mma16(float* c, const uint4& a, uint32_t b0, uint32_t b1) {
    asm volatile(
        "mma.sync.aligned.m16n8k16.row.col.f32.f16.f16.f32 "
        "{%0,%1,%2,%3},{%4,%5,%6,%7},{%8,%9},{%0,%1,%2,%3};\n"
        : "+f"(c[0]), "+f"(c[1]), "+f"(c[2]), "+f"(c[3])
        : "r"(a.x), "r"(a.y), "r"(a.z), "r"(a.w), "r"(b0), "r"(b1));
}

// A-fragment lane swizzle (conflict-free for gen STS.128 and consumer LDS.128)
__device__ __forceinline__ uint32_t a_lswz(uint32_t lane_c) {
    return (lane_c * 16u) ^ (((lane_c >> 3) & 3u) << 4);
}

// ---------------------------------------------------------------- prologues
// B fragments (fp16, scaled by 2^12) + per-block bias partials (coalesced).
__global__ void __launch_bounds__(256) prep_kernel(const float* __restrict__ coef) {
    extern __shared__ float sbuf[];                    // 72KB rows + 32KB stg
    float* rows = sbuf;                                // [2][9216]
    uint32_t* stg = reinterpret_cast<uint32_t*>(sbuf + 18432);
    const int b = blockIdx.x;
    const int c = b >> 2, s = b & 3;
    const int i0 = c * 8 + s * 2;
    {
        const float4* src4 = reinterpret_cast<const float4*>(coef + (size_t)i0 * 9216);
        float4* dst4 = reinterpret_cast<float4*>(rows);
        #pragma unroll
        for (int k = 0; k < 18; k++)
            dst4[threadIdx.x + (k << 8)] = src4[threadIdx.x + (k << 8)];
    }
    __syncthreads();
    #pragma unroll
    for (int r = 0; r < 4; r++) {
        const int col = threadIdx.x + (r << 8);
        const float* cv0 = rows + col * 9;             // stride 9 coprime 32
        const float* cv1 = rows + 9216 + col * 9;
        const int g = col & 7, colpar = (col >> 3) & 1;
        const int nip = (col >> 4) & 3, wnG = col >> 6;
        const int base = wnG * 512 + nip * 128 + colpar * 2;
        #pragma unroll
        for (int t = 0; t < 4; t++) {
            stg[base + (g * 4 + t) * 4 + 0] =
                h2pack(cv0[2 * t + 1] * CSCALE, cv0[2 * t + 2] * CSCALE);
            stg[base + (g * 4 + t) * 4 + 1] =
                h2pack(cv1[2 * t + 1] * CSCALE, cv1[2 * t + 2] * CSCALE);
        }
        g_part[(size_t)b * OUT_F + col] = cv0[0] + cv1[0];   // bias partial
    }
    __syncthreads();
    float4* dst = reinterpret_cast<float4*>(g_BF);
    const float4* src = reinterpret_cast<const float4*>(stg);
    #pragma unroll
    for (int k = 0; k < 8; k++) {
        const int q = threadIdx.x + (k << 8);   // 0..2047
        const int wnG = q >> 7, inner = q & 127;
        dst[(size_t)(c * 16 + wnG) * 512 + s * 128 + inner] = src[q];
    }
}

// bias[o] = sum over 512 partials (deterministic fixed order)
__global__ void __launch_bounds__(256) bias_red_kernel() {
    const int o = (blockIdx.x << 8) + threadIdx.x;
    float s0 = 0.f, s1 = 0.f, s2 = 0.f, s3 = 0.f;
    #pragma unroll 4
    for (int b = 0; b < 512; b += 4) {
        s0 += g_part[(size_t)(b + 0) * OUT_F + o];
        s1 += g_part[(size_t)(b + 1) * OUT_F + o];
        s2 += g_part[(size_t)(b + 2) * OUT_F + o];
        s3 += g_part[(size_t)(b + 3) * OUT_F + o];
    }
    g_bias[o] = (s0 + s1) + (s2 + s3);
}

// ---------------------------------------------------------------- main GEMM
// 1024 CTAs: unit u = bmIdx*16 + kq*4 + bx. Each computes the K-range
// [kq*2048,(kq+1)*2048) partial for tile (bm=bmIdx*128, bn=bx*256).
__global__ void __launch_bounds__(NTHR, 1) cheby_main(const float* __restrict__ X,
                                                      float* __restrict__ Out) {
    extern __shared__ uint8_t sm[];
    __shared__ int s_last;
    const uint32_t smA = (uint32_t)__cvta_generic_to_shared(sm);          // 4 x 16KB
    const uint32_t smB = smA + NSTG * A_BYTES;                            // 4 x 32KB

    const int tid  = threadIdx.x;
    const int lane = tid & 31;
    const int w    = tid >> 5;
    const int u     = blockIdx.x;
    const int bx    = u & 3;
    const int kq    = (u >> 2) & 3;
    const int bmIdx = u >> 4;
    const int bm    = bmIdx << 7;

    const float4* bsrc = reinterpret_cast<const float4*>(g_BF);

    if (w < 8) {
        // ======================= CONSUMER (256 threads) =====================
        const int wm = w >> 2;           // 0..1 (64-row block)
        const int wn = w & 3;            // 0..3 (64-col block)
        const int g  = lane >> 2;
        const int t  = lane & 3;
        const uint32_t lsw = a_lswz((uint32_t)lane);

        float acc[4][8][4];
        #pragma unroll
        for (int mi = 0; mi < 4; mi++)
            #pragma unroll
            for (int ni = 0; ni < 8; ni++)
                #pragma unroll
                for (int q = 0; q < 4; q++) acc[mi][ni][q] = 0.f;

        for (int c = 0; c < NCHUNK; c++) {
            const int st = c & 3;
            bar_sync_id(1 + st);                 // wait stage FULL
            const uint32_t aBase = smA + (uint32_t)(st * A_BYTES + wm * 2048) + lsw;
            const uint32_t bBase = smB + (uint32_t)(st * B_BYTES + wn * 8192 + lane * 16);

            #pragma unroll
            for (int s = 0; s < 4; s++) {
                uint4 aC[4];
                #pragma unroll
                for (int mi = 0; mi < 4; mi++)
                    lds128(aC[mi], aBase + (uint32_t)(s * 4096 + mi * 512));
                uint4 bC[4];
                #pragma unroll
                for (int nip = 0; nip < 4; nip++)
                    lds128(bC[nip], bBase + (uint32_t)(s * 2048 + nip * 512));
                #pragma unroll
                for (int ni = 0; ni < 8; ni++) {
                    const uint32_t b0 = (ni & 1) ? bC[ni >> 1].z : bC[ni >> 1].x;
                    const uint32_t b1 = (ni & 1) ? bC[ni >> 1].w : bC[ni >> 1].y;
                    #pragma unroll
                    for (int mi = 0; mi < 4; mi++)
                        mma16(acc[mi][ni], aC[mi], b0, b1);
                }
            }
            bar_arrive_id(5 + st);               // stage FREE
        }

        // --- epilogue A: store raw fp32 partial for this (tile, kq) ---
        float* pt = g_Pt + (size_t)u * 32768;
        #pragma unroll
        for (int ni = 0; ni < 8; ni++) {
            const int ccl = (wn << 6) + (ni << 3) + (t << 1);
            #pragma unroll
            for (int mi = 0; mi < 4; mi++) {
                const int r0 = (wm << 6) + (mi << 4) + g;
                float2 o0 = { acc[mi][ni][0], acc[mi][ni][1] };
                float2 o1 = { acc[mi][ni][2], acc[mi][ni][3] };
                *reinterpret_cast<float2*>(pt + r0 * BN + ccl)        = o0;
                *reinterpret_cast<float2*>(pt + (r0 + 8) * BN + ccl)  = o1;
            }
        }
        __threadfence();                 // publish this thread's partial stores
        bar_sync_cons();                 // all consumer stores fenced
        if (tid == 0) {
            const int tile = (bmIdx << 2) + bx;
            s_last = (atomicAdd(&g_tk[tile], 1) == 3);
        }
        bar_sync_cons();

        // --- epilogue B: last-arriving CTA reduces all 4 kq partials ---
        if (s_last) {
            __threadfence();             // acquire side: partials visible
            const float4* p4 = reinterpret_cast<const float4*>(g_Pt);
            const size_t base0 = ((size_t)((bmIdx << 4) + 0 + bx)) * 8192;
            const size_t base1 = ((size_t)((bmIdx << 4) + 4 + bx)) * 8192;
            const size_t base2 = ((size_t)((bmIdx << 4) + 8 + bx)) * 8192;
            const size_t base3 = ((size_t)((bmIdx << 4) + 12 + bx)) * 8192;
            const int bnB = bx << 8;
            #pragma unroll 4
            for (int k = 0; k < 32; k++) {
                const int q  = tid + (k << 8);       // 0..8191 (float4 of tile)
                const int r  = q >> 6;               // local row
                const int c4 = q & 63;               // float4 col
                float4 p0 = p4[base0 + q];
                float4 p1 = p4[base1 + q];
                float4 p2 = p4[base2 + q];
                float4 p3 = p4[base3 + q];
                const float4 bv = *reinterpret_cast<const float4*>(g_bias + bnB + c4 * 4);
                float4 o;
                o.x = fmaf(((p0.x + p1.x) + p2.x) + p3.x, OSCALE, bv.x);
                o.y = fmaf(((p0.y + p1.y) + p2.y) + p3.y, OSCALE, bv.y);
                o.z = fmaf(((p0.z + p1.z) + p2.z) + p3.z, OSCALE, bv.z);
                o.w = fmaf(((p0.w + p1.w) + p2.w) + p3.w, OSCALE, bv.w);
                *reinterpret_cast<float4*>(Out + (size_t)(bm + r) * OUT_F + bnB + c4 * 4) = o;
            }
            if (tid == 0) g_tk[(bmIdx << 2) + bx] = 0;   // re-arm for next launch
        }
    } else {
        // ======================= PRODUCER (128 threads) =====================
        const int ptid = tid - 256;
        // 2 generator units per thread: u = ptid, ptid+128
        // unit: s = u&3, g = (u>>2)&7, G = u>>5; rows G*16+g, +8

        #define PRODUCE(n)                                                        \
        do {                                                                      \
            const int st_ = (n) & 3;                                              \
            const int gc_ = (kq << 5) + (n);     /* global KC64 chunk */          \
            const uint32_t dstB_ = smB + (uint32_t)(st_ * B_BYTES);               \
            _Pragma("unroll")                                                     \
            for (int k = 0; k < 16; k++) {                                        \
                const int wng = k >> 2;                                           \
                const int inner = ptid + ((k & 3) << 7);                          \
                cpa16(dstB_ + (uint32_t)(wng * 8192 + inner * 16),                \
                      bsrc + (size_t)(gc_ * 16 + (bx << 2) + wng) * 512 + inner); \
            }                                                                     \
            cpa_commit();                                                         \
            const uint32_t aDst_ = smA + (uint32_t)(st_ * A_BYTES);               \
            _Pragma("unroll")                                                     \
            for (int e = 0; e < 2; e++) {                                         \
                const int uu = ptid + (e << 7);                                   \
                const int s_ = uu & 3, g_ = (uu >> 2) & 7, G_ = uu >> 5;          \
                const int rA = bm + (G_ << 4) + g_;                               \
                const float2 xA = *reinterpret_cast<const float2*>(               \
                    X + (size_t)rA * IN_F + (gc_ << 3) + (s_ << 1));              \
                const float2 xB = *reinterpret_cast<const float2*>(               \
                    X + (size_t)(rA + 8) * IN_F + (gc_ << 3) + (s_ << 1));        \
                const float tA0 = fast_tanh(xA.x), tA1 = fast_tanh(xA.y);         \
                const float tB0 = fast_tanh(xB.x), tB1 = fast_tanh(xB.y);         \
                float TA0[8], TA1[8], TB0[8], TB1[8];                             \
                TA0[0] = tA0; TA1[0] = tA1; TB0[0] = tB0; TB1[0] = tB1;           \
                TA0[1] = 2.f * tA0 * tA0 - 1.f;                                   \
                TA1[1] = 2.f * tA1 * tA1 - 1.f;                                   \
                TB0[1] = 2.f * tB0 * tB0 - 1.f;                                   \
                TB1[1] = 2.f * tB1 * tB1 - 1.f;                                   \
                _Pragma("unroll")                                                 \
                for (int d = 2; d < 8; d++) {                                     \
                    TA0[d] = 2.f * tA0 * TA0[d - 1] - TA0[d - 2];                 \
                    TA1[d] = 2.f * tA1 * TA1[d - 1] - TA1[d - 2];                 \
                    TB0[d] = 2.f * tB0 * TB0[d - 1] - TB0[d - 2];                 \
                    TB1[d] = 2.f * tB1 * TB1[d - 1] - TB1[d - 2];                 \
                }                                                                 \
                const uint32_t ab_ = aDst_ + (uint32_t)(s_ * 4096 + G_ * 512);    \
                _Pragma("unroll")                                                 \
                for (int t = 0; t < 4; t++)                                       \
                    sts128(ab_ + a_lswz((uint32_t)(g_ * 4 + t)),                  \
                           h2pack(TA0[2 * t], TA0[2 * t + 1]),                    \
                           h2pack(TB0[2 * t], TB0[2 * t + 1]),                    \
                           h2pack(TA1[2 * t], TA1[2 * t + 1]),                    \
                           h2pack(TB1[2 * t], TB1[2 * t + 1]));                   \
            }                                                                     \
        } while (0)

        // n=0: no FREE wait, no arrive yet
        PRODUCE(0);
        for (int n = 1; n < NCHUNK; n++) {
            if (n >= NSTG) bar_sync_id(5 + (n & 3));   // wait stage FREE
            PRODUCE(n);
            cpa_wait<1>();                              // group n-1 drained
            bar_arrive_id(1 + ((n - 1) & 3));           // stage n-1 FULL
        }
        cpa_wait<0>();                                  // last group drained
        bar_arrive_id(1 + ((NCHUNK - 1) & 3));          // last stage FULL
        #undef PRODUCE
    }
}

// --------------------------------------------------------------------------
extern "C" void kernel_launch(void* const* d_in, const int* in_sizes, int n_in,
                              void* d_out, int out_size) {
    (void)in_sizes; (void)n_in; (void)out_size;
    const float* x    = (const float*)d_in[0];
    const float* coef = (const float*)d_in[1];
    float* out        = (float*)d_out;

    const int smem_bytes = NSTG * STAGE_BYTES;   // 196608
    cudaFuncSetAttribute(cheby_main, cudaFuncAttributeMaxDynamicSharedMemorySize,
                         smem_bytes);
    const int prep_smem = 18432 * 4 + 8192 * 4;  // 106496
    cudaFuncSetAttribute(prep_kernel, cudaFuncAttributeMaxDynamicSharedMemorySize,
                         prep_smem);

    prep_kernel<<<512, 256, prep_smem>>>(coef);
    bias_red_kernel<<<4, 256>>>();
    cheby_main<<<1024, NTHR, smem_bytes>>>(x, out);
}

// round 16
// speedup vs baseline: 1.1328x; 1.1152x over previous
#include <cuda_runtime.h>
#include <cuda_fp16.h>
#include <cstdint>

// ===========================================================================
// ChebyKANLinear, mma.sync m16n8k16 FP16 (fp32 accumulate).
// R15: persistent CTAs (grid = #SMs), contiguous chunk-range partitioning of
// the 32768 global KC64 chunk-units -> 99.7% load balance. Tiles straddling
// a CTA boundary (<=2 CTAs each) use the R14-proven partial+ticket+combine;
// interior tiles write Out directly. Ring/barrier/MMA/producer = R11 exactly.
// ===========================================================================

#define BATCH   8192
#define IN_F    1024
#define OUT_F   1024
#define BM      128
#define BN      256
#define KC      64
#define NTOT    32768          // 256 tiles * 128 chunks
#define A_BYTES 16384          // BM * KC * 2 (fp16)
#define B_BYTES 32768          // BN * KC * 2 (fp16)
#define STAGE_BYTES (A_BYTES + B_BYTES)
#define NSTG    4
#define NTHR    384
#define CSCALE  4096.0f
#define OSCALE  (1.0f / 4096.0f)

// Static device scratch (no runtime allocation allowed)
__device__ uint32_t g_BF[(size_t)128 * 16 * 2048];    // B fp16 frags, 16 MB
__device__ float g_Ps[(size_t)256 * 2 * 32768];       // straddle partials, 64 MB
__device__ float g_part[512 * OUT_F];                 // bias partials, 2 MB
__device__ float g_bias[OUT_F];
__device__ int   g_tk[256];                           // per-tile tickets (0-init)

// ---------------------------------------------------------------- utils
__device__ __forceinline__ uint32_t h2pack(float lo, float hi) {
    __half2 h = __floats2half2_rn(lo, hi);
    return *reinterpret_cast<uint32_t*>(&h);
}
__device__ __forceinline__ float fast_tanh(float x) {
    float e = __expf(2.f * x);
    return 1.f - __fdividef(2.f, e + 1.f);
}
__device__ __forceinline__ void cpa16(uint32_t dst, const void* src) {
    asm volatile("cp.async.cg.shared.global [%0], [%1], 16;\n" :: "r"(dst), "l"(src));
}
__device__ __forceinline__ void cpa_commit() { asm volatile("cp.async.commit_group;\n"); }
template <int N>
__device__ __forceinline__ void cpa_wait() {
    asm volatile("cp.async.wait_group %0;\n" :: "n"(N) : "memory");
}
// Split named barriers (384): FULL[s]=1+s, FREE[s]=5+s. Consumer-only: id 9.
__device__ __forceinline__ void bar_sync_id(int id) {
    asm volatile("bar.sync %0, %1;" :: "r"(id), "n"(NTHR) : "memory");
}
__device__ __forceinline__ void bar_arrive_id(int id) {
    asm volatile("bar.arrive %0, %1;" :: "r"(id), "n"(NTHR) : "memory");
}
__device__ __forceinline__ void bar_sync_cons() {
    asm volatile("bar.sync 9, 256;" ::: "memory");
}
__device__ __forceinline__ void lds128(uint4& v, uint32_t addr) {
    asm volatile("ld.shared.v4.b32 {%0,%1,%2,%3}, [%4];"
                 : "=r"(v.x), "=r"(v.y), "=r"(v.z), "=r"(v.w) : "r"(addr));
}
__device__ __forceinline__ void sts128(uint32_t addr, uint32_t a, uint32_t b,
                                       uint32_t c, uint32_t d) {
    asm volatile("st.shared.v4.b32 [%0], {%1,%2,%3,%4};"
                 :: "r"(addr), "r"(a), "r"(b), "r"(c), "r"(d));
}
__device__ __forceinline__ void mma16(float* c, const uint4& a, uint32_t b0, uint32_t b1) {
    asm volatile(
        "mma.sync.aligned.m16n8k16.row.col.f32.f16.f16.f32 "
        "{%0,%1,%2,%3},{%4,%5,%6,%7},{%8,%9},{%0,%1,%2,%3};\n"
        : "+f"(c[0]), "+f"(c[1]), "+f"(c[2]), "+f"(c[3])
        : "r"(a.x), "r"(a.y), "r"(a.z), "r"(a.w), "r"(b0), "r"(b1));
}
__device__ __forceinline__ uint32_t a_lswz(uint32_t lane_c) {
    return (lane_c * 16u) ^ (((lane_c >> 3) & 3u) << 4);
}

// ---------------------------------------------------------------- prologues
__global__ void __launch_bounds__(256) prep_kernel(const float* __restrict__ coef) {
    extern __shared__ float sbuf[];                    // 72KB rows + 32KB stg
    float* rows = sbuf;
    uint32_t* stg = reinterpret_cast<uint32_t*>(sbuf + 18432);
    const int b = blockIdx.x;
    const int c = b >> 2, s = b & 3;
    const int i0 = c * 8 + s * 2;
    {
        const float4* src4 = reinterpret_cast<const float4*>(coef + (size_t)i0 * 9216);
        float4* dst4 = reinterpret_cast<float4*>(rows);
        #pragma unroll
        for (int k = 0; k < 18; k++)
            dst4[threadIdx.x + (k << 8)] = src4[threadIdx.x + (k << 8)];
    }
    __syncthreads();
    #pragma unroll
    for (int r = 0; r < 4; r++) {
        const int col = threadIdx.x + (r << 8);
        const float* cv0 = rows + col * 9;
        const float* cv1 = rows + 9216 + col * 9;
        const int g = col & 7, colpar = (col >> 3) & 1;
        const int nip = (col >> 4) & 3, wnG = col >> 6;
        const int base = wnG * 512 + nip * 128 + colpar * 2;
        #pragma unroll
        for (int t = 0; t < 4; t++) {
            stg[base + (g * 4 + t) * 4 + 0] =
                h2pack(cv0[2 * t + 1] * CSCALE, cv0[2 * t + 2] * CSCALE);
            stg[base + (g * 4 + t) * 4 + 1] =
                h2pack(cv1[2 * t + 1] * CSCALE, cv1[2 * t + 2] * CSCALE);
        }
        g_part[(size_t)b * OUT_F + col] = cv0[0] + cv1[0];
    }
    __syncthreads();
    float4* dst = reinterpret_cast<float4*>(g_BF);
    const float4* src = reinterpret_cast<const float4*>(stg);
    #pragma unroll
    for (int k = 0; k < 8; k++) {
        const int q = threadIdx.x + (k << 8);
        const int wnG = q >> 7, inner = q & 127;
        dst[(size_t)(c * 16 + wnG) * 512 + s * 128 + inner] = src[q];
    }
}

__global__ void __launch_bounds__(256) bias_red_kernel() {
    const int o = (blockIdx.x << 8) + threadIdx.x;
    float s0 = 0.f, s1 = 0.f, s2 = 0.f, s3 = 0.f;
    #pragma unroll 4
    for (int b = 0; b < 512; b += 4) {
        s0 += g_part[(size_t)(b + 0) * OUT_F + o];
        s1 += g_part[(size_t)(b + 1) * OUT_F + o];
        s2 += g_part[(size_t)(b + 2) * OUT_F + o];
        s3 += g_part[(size_t)(b + 3) * OUT_F + o];
    }
    g_bias[o] = (s0 + s1) + (s2 + s3);
}

// ---------------------------------------------------------------- producer
__device__ __forceinline__ void produce_chunk(int n, int ptid,
                                              const float* __restrict__ X,
                                              const float4* __restrict__ bsrc,
                                              uint32_t smA, uint32_t smB) {
    const int st   = n & 3;
    const int tile = n >> 7;
    const int kc   = n & 127;
    const int bmP  = (tile >> 2) << 7;
    const int bxP  = tile & 3;
    // B: 4 wnG blocks of 512 float4
    const uint32_t dstB = smB + (uint32_t)(st * B_BYTES);
    #pragma unroll
    for (int k = 0; k < 16; k++) {
        const int wng = k >> 2;
        const int inner = ptid + ((k & 3) << 7);
        cpa16(dstB + (uint32_t)(wng * 8192 + inner * 16),
              bsrc + (size_t)(kc * 16 + (bxP << 2) + wng) * 512 + inner);
    }
    cpa_commit();
    // A generation with fused tanh
    const uint32_t aDst = smA + (uint32_t)(st * A_BYTES);
    #pragma unroll
    for (int e = 0; e < 2; e++) {
        const int u = ptid + (e << 7);
        const int s_ = u & 3, g_ = (u >> 2) & 7, G_ = u >> 5;
        const int rA = bmP + (G_ << 4) + g_;
        const float2 xA = *reinterpret_cast<const float2*>(
            X + (size_t)rA * IN_F + (kc << 3) + (s_ << 1));
        const float2 xB = *reinterpret_cast<const float2*>(
            X + (size_t)(rA + 8) * IN_F + (kc << 3) + (s_ << 1));
        const float tA0 = fast_tanh(xA.x), tA1 = fast_tanh(xA.y);
        const float tB0 = fast_tanh(xB.x), tB1 = fast_tanh(xB.y);
        float TA0[8], TA1[8], TB0[8], TB1[8];
        TA0[0] = tA0; TA1[0] = tA1; TB0[0] = tB0; TB1[0] = tB1;
        TA0[1] = 2.f * tA0 * tA0 - 1.f;
        TA1[1] = 2.f * tA1 * tA1 - 1.f;
        TB0[1] = 2.f * tB0 * tB0 - 1.f;
        TB1[1] = 2.f * tB1 * tB1 - 1.f;
        #pragma unroll
        for (int d = 2; d < 8; d++) {
            TA0[d] = 2.f * tA0 * TA0[d - 1] - TA0[d - 2];
            TA1[d] = 2.f * tA1 * TA1[d - 1] - TA1[d - 2];
            TB0[d] = 2.f * tB0 * TB0[d - 1] - TB0[d - 2];
            TB1[d] = 2.f * tB1 * TB1[d - 1] - TB1[d - 2];
        }
        const uint32_t ab = aDst + (uint32_t)(s_ * 4096 + G_ * 512);
        #pragma unroll
        for (int t = 0; t < 4; t++)
            sts128(ab + a_lswz((uint32_t)(g_ * 4 + t)),
                   h2pack(TA0[2 * t], TA0[2 * t + 1]),
                   h2pack(TB0[2 * t], TB0[2 * t + 1]),
                   h2pack(TA1[2 * t], TA1[2 * t + 1]),
                   h2pack(TB1[2 * t], TB1[2 * t + 1]));
    }
}

// ---------------------------------------------------------------- main GEMM
__global__ void __launch_bounds__(NTHR, 1) cheby_main(const float* __restrict__ X,
                                                      float* __restrict__ Out) {
    extern __shared__ uint8_t sm[];
    __shared__ int s_last;
    const uint32_t smA = (uint32_t)__cvta_generic_to_shared(sm);          // 4 x 16KB
    const uint32_t smB = smA + NSTG * A_BYTES;                            // 4 x 32KB

    const int tid  = threadIdx.x;
    const int lane = tid & 31;
    const int w    = tid >> 5;
    const int p    = blockIdx.x;
    const int G    = gridDim.x;
    const int q0   = (int)(((long long)p * NTOT) / G);
    const int q1   = (int)(((long long)(p + 1) * NTOT) / G);

    const float4* bsrc = reinterpret_cast<const float4*>(g_BF);

    if (w < 8) {
        // ======================= CONSUMER (256 threads) =====================
        const int wm = w >> 2;
        const int wn = w & 3;
        const int g  = lane >> 2;
        const int t  = lane & 3;
        const uint32_t lsw = a_lswz((uint32_t)lane);

        int j = q0;
        while (j < q1) {
            const int tile = j >> 7;
            const int c0   = j & 127;
            const int rem  = q1 - j;
            const int cend = (c0 + rem < 128) ? (c0 + rem) : 128;

            float acc[4][8][4];
            #pragma unroll
            for (int mi = 0; mi < 4; mi++)
                #pragma unroll
                for (int ni = 0; ni < 8; ni++)
                    #pragma unroll
                    for (int q = 0; q < 4; q++) acc[mi][ni][q] = 0.f;

            for (int c = c0; c < cend; c++, j++) {
                const int st = j & 3;
                bar_sync_id(1 + st);
                const uint32_t aBase = smA + (uint32_t)(st * A_BYTES + wm * 2048) + lsw;
                const uint32_t bBase = smB + (uint32_t)(st * B_BYTES + wn * 8192 + lane * 16);
                #pragma unroll
                for (int s = 0; s < 4; s++) {
                    uint4 aC[4];
                    #pragma unroll
                    for (int mi = 0; mi < 4; mi++)
                        lds128(aC[mi], aBase + (uint32_t)(s * 4096 + mi * 512));
                    uint4 bC[4];
                    #pragma unroll
                    for (int nip = 0; nip < 4; nip++)
                        lds128(bC[nip], bBase + (uint32_t)(s * 2048 + nip * 512));
                    #pragma unroll
                    for (int ni = 0; ni < 8; ni++) {
                        const uint32_t b0 = (ni & 1) ? bC[ni >> 1].z : bC[ni >> 1].x;
                        const uint32_t b1 = (ni & 1) ? bC[ni >> 1].w : bC[ni >> 1].y;
                        #pragma unroll
                        for (int mi = 0; mi < 4; mi++)
                            mma16(acc[mi][ni], aC[mi], b0, b1);
                    }
                }
                bar_arrive_id(5 + st);
            }

            // ---- epilogue for this segment ----
            const int bm = (tile >> 2) << 7;
            const int bn = (tile & 3) << 8;
            if (c0 == 0 && cend == 128) {
                // full tile owned: direct write with bias + scale
                #pragma unroll
                for (int ni = 0; ni < 8; ni++) {
                    const int cc = bn + (wn << 6) + (ni << 3) + (t << 1);
                    const float2 bv = *reinterpret_cast<const float2*>(g_bias + cc);
                    #pragma unroll
                    for (int mi = 0; mi < 4; mi++) {
                        const int r0 = bm + (wm << 6) + (mi << 4) + g;
                        float2 o0 = { fmaf(acc[mi][ni][0], OSCALE, bv.x),
                                      fmaf(acc[mi][ni][1], OSCALE, bv.y) };
                        float2 o1 = { fmaf(acc[mi][ni][2], OSCALE, bv.x),
                                      fmaf(acc[mi][ni][3], OSCALE, bv.y) };
                        *reinterpret_cast<float2*>(Out + (size_t)r0 * OUT_F + cc)       = o0;
                        *reinterpret_cast<float2*>(Out + (size_t)(r0 + 8) * OUT_F + cc) = o1;
                    }
                }
            } else {
                // straddled: write raw partial (half 0 = lo = starts at kc 0)
                const int half = (c0 == 0) ? 0 : 1;
                float* pt = g_Ps + ((size_t)tile * 2 + half) * 32768;
                #pragma unroll
                for (int ni = 0; ni < 8; ni++) {
                    const int ccl = (wn << 6) + (ni << 3) + (t << 1);
                    #pragma unroll
                    for (int mi = 0; mi < 4; mi++) {
                        const int r0 = (wm << 6) + (mi << 4) + g;
                        float2 o0 = { acc[mi][ni][0], acc[mi][ni][1] };
                        float2 o1 = { acc[mi][ni][2], acc[mi][ni][3] };
                        *reinterpret_cast<float2*>(pt + r0 * BN + ccl)       = o0;
                        *reinterpret_cast<float2*>(pt + (r0 + 8) * BN + ccl) = o1;
                    }
                }
                __threadfence();
                bar_sync_cons();
                if (tid == 0) s_last = (atomicAdd(&g_tk[tile], 1) == 1);
                bar_sync_cons();
                if (s_last) {
                    __threadfence();
                    const float4* p4 = reinterpret_cast<const float4*>(g_Ps);
                    const size_t bLo = ((size_t)tile * 2 + 0) * 8192;
                    const size_t bHi = ((size_t)tile * 2 + 1) * 8192;
                    #pragma unroll 4
                    for (int k = 0; k < 32; k++) {
                        const int q  = tid + (k << 8);   // 0..8191 float4 of tile
                        const int r  = q >> 6;
                        const int c4 = q & 63;
                        const float4 lo = p4[bLo + q];
                        const float4 hi = p4[bHi + q];
                        const float4 bv = *reinterpret_cast<const float4*>(
                            g_bias + bn + c4 * 4);
                        float4 o;
                        o.x = fmaf(lo.x + hi.x, OSCALE, bv.x);
                        o.y = fmaf(lo.y + hi.y, OSCALE, bv.y);
                        o.z = fmaf(lo.z + hi.z, OSCALE, bv.z);
                        o.w = fmaf(lo.w + hi.w, OSCALE, bv.w);
                        *reinterpret_cast<float4*>(
                            Out + (size_t)(bm + r) * OUT_F + bn + c4 * 4) = o;
                    }
                    if (tid == 0) g_tk[tile] = 0;   // re-arm for next launch
                }
            }
        }
    } else {
        // ======================= PRODUCER (128 threads) =====================
        const int ptid = tid - 256;
        produce_chunk(q0, ptid, X, bsrc, smA, smB);
        for (int n = q0 + 1; n < q1; n++) {
            if (n >= q0 + NSTG) bar_sync_id(5 + (n & 3));   // wait stage FREE
            produce_chunk(n, ptid, X, bsrc, smA, smB);
            cpa_wait<1>();                                   // group n-1 drained
            bar_arrive_id(1 + ((n - 1) & 3));                // stage n-1 FULL
        }
        cpa_wait<0>();
        bar_arrive_id(1 + ((q1 - 1) & 3));
    }
}

// --------------------------------------------------------------------------
extern "C" void kernel_launch(void* const* d_in, const int* in_sizes, int n_in,
                              void* d_out, int out_size) {
    (void)in_sizes; (void)n_in; (void)out_size;
    const float* x    = (const float*)d_in[0];
    const float* coef = (const float*)d_in[1];
    float* out        = (float*)d_out;

    const int smem_bytes = NSTG * STAGE_BYTES;   // 196608
    cudaFuncSetAttribute(cheby_main, cudaFuncAttributeMaxDynamicSharedMemorySize,
                         smem_bytes);
    const int prep_smem = 18432 * 4 + 8192 * 4;  // 106496
    cudaFuncSetAttribute(prep_kernel, cudaFuncAttributeMaxDynamicSharedMemorySize,
                         prep_smem);

    int nsm = 148;
    cudaDeviceGetAttribute(&nsm, cudaDevAttrMultiProcessorCount, 0);
    if (nsm < 32 || nsm > 256) nsm = 148;

    prep_kernel<<<512, 256, prep_smem>>>(coef);
    bias_red_kernel<<<4, 256>>>();
    cheby_main<<<nsm, NTHR, smem_bytes>>>(x, out);
}

// round 17
// speedup vs baseline: 1.1404x; 1.0067x over previous
#include <cuda_runtime.h>
#include <cuda_fp16.h>
#include <cstdint>

// ===========================================================================
// ChebyKANLinear, mma.sync m16n8k16 FP16 (fp32 accumulate).
// R16: R15 main kernel untouched (383.7us, ~93% of saturated-HMMA floor).
// prep_kernel split into column-halves: 52KB smem -> 4 CTAs/SM (was 106KB/
// 1 CTA/SM at 28% HBM). Expect prep 16.8 -> ~10us.
// ===========================================================================

#define BATCH   8192
#define IN_F    1024
#define OUT_F   1024
#define BM      128
#define BN      256
#define KC      64
#define NTOT    32768          // 256 tiles * 128 chunks
#define A_BYTES 16384          // BM * KC * 2 (fp16)
#define B_BYTES 32768          // BN * KC * 2 (fp16)
#define STAGE_BYTES (A_BYTES + B_BYTES)
#define NSTG    4
#define NTHR    384
#define CSCALE  4096.0f
#define OSCALE  (1.0f / 4096.0f)

// Static device scratch (no runtime allocation allowed)
__device__ uint32_t g_BF[(size_t)128 * 16 * 2048];    // B fp16 frags, 16 MB
__device__ float g_Ps[(size_t)256 * 2 * 32768];       // straddle partials, 64 MB
__device__ float g_part[512 * OUT_F];                 // bias partials, 2 MB
__device__ float g_bias[OUT_F];
__device__ int   g_tk[256];                           // per-tile tickets (0-init)

// ---------------------------------------------------------------- utils
__device__ __forceinline__ uint32_t h2pack(float lo, float hi) {
    __half2 h = __floats2half2_rn(lo, hi);
    return *reinterpret_cast<uint32_t*>(&h);
}
__device__ __forceinline__ float fast_tanh(float x) {
    float e = __expf(2.f * x);
    return 1.f - __fdividef(2.f, e + 1.f);
}
__device__ __forceinline__ void cpa16(uint32_t dst, const void* src) {
    asm volatile("cp.async.cg.shared.global [%0], [%1], 16;\n" :: "r"(dst), "l"(src));
}
__device__ __forceinline__ void cpa_commit() { asm volatile("cp.async.commit_group;\n"); }
template <int N>
__device__ __forceinline__ void cpa_wait() {
    asm volatile("cp.async.wait_group %0;\n" :: "n"(N) : "memory");
}
// Split named barriers (384): FULL[s]=1+s, FREE[s]=5+s. Consumer-only: id 9.
__device__ __forceinline__ void bar_sync_id(int id) {
    asm volatile("bar.sync %0, %1;" :: "r"(id), "n"(NTHR) : "memory");
}
__device__ __forceinline__ void bar_arrive_id(int id) {
    asm volatile("bar.arrive %0, %1;" :: "r"(id), "n"(NTHR) : "memory");
}
__device__ __forceinline__ void bar_sync_cons() {
    asm volatile("bar.sync 9, 256;" ::: "memory");
}
__device__ __forceinline__ void lds128(uint4& v, uint32_t addr) {
    asm volatile("ld.shared.v4.b32 {%0,%1,%2,%3}, [%4];"
                 : "=r"(v.x), "=r"(v.y), "=r"(v.z), "=r"(v.w) : "r"(addr));
}
__device__ __forceinline__ void sts128(uint32_t addr, uint32_t a, uint32_t b,
                                       uint32_t c, uint32_t d) {
    asm volatile("st.shared.v4.b32 [%0], {%1,%2,%3,%4};"
                 :: "r"(addr), "r"(a), "r"(b), "r"(c), "r"(d));
}
__device__ __forceinline__ void mma16(float* c, const uint4& a, uint32_t b0, uint32_t b1) {
    asm volatile(
        "mma.sync.aligned.m16n8k16.row.col.f32.f16.f16.f32 "
        "{%0,%1,%2,%3},{%4,%5,%6,%7},{%8,%9},{%0,%1,%2,%3};\n"
        : "+f"(c[0]), "+f"(c[1]), "+f"(c[2]), "+f"(c[3])
        : "r"(a.x), "r"(a.y), "r"(a.z), "r"(a.w), "r"(b0), "r"(b1));
}
__device__ __forceinline__ uint32_t a_lswz(uint32_t lane_c) {
    return (lane_c * 16u) ^ (((lane_c >> 3) & 3u) << 4);
}

// ---------------------------------------------------------------- prologues
// R16 prep: 1024 blocks; block b = (ip, h): i-pair ip = b>>1, column half
// h = b&1 (cols [h*512, h*512+512)). 52KB dynamic smem -> 4 CTAs/SM.
__global__ void __launch_bounds__(256) prep_kernel(const float* __restrict__ coef) {
    extern __shared__ float sbuf[];                    // 36KB rows + 16KB stg
    float* rows = sbuf;                                // [2][512*9]
    uint32_t* stg = reinterpret_cast<uint32_t*>(sbuf + 9216);   // 4096 words
    const int b  = blockIdx.x;
    const int ip = b >> 1, h = b & 1;
    const int c  = ip >> 2, s = ip & 3;
    const int i0 = c * 8 + s * 2;

    // coalesced stage: both rows' col-half segments (1152 float4 each)
    {
        const float4* s0 = reinterpret_cast<const float4*>(
            coef + (size_t)i0 * 9216 + h * 4608);
        const float4* s1 = reinterpret_cast<const float4*>(
            coef + (size_t)(i0 + 1) * 9216 + h * 4608);
        float4* r0 = reinterpret_cast<float4*>(rows);
        float4* r1 = r0 + 1152;
        #pragma unroll
        for (int k = 0; k < 5; k++) {
            const int idx = threadIdx.x + (k << 8);
            if (idx < 1152) { r0[idx] = s0[idx]; r1[idx] = s1[idx]; }
        }
    }
    __syncthreads();
    #pragma unroll
    for (int r = 0; r < 2; r++) {
        const int col  = threadIdx.x + (r << 8);       // local 0..511
        const int gcol = (h << 9) + col;
        const float* cv0 = rows + col * 9;             // stride 9 coprime 32
        const float* cv1 = rows + 4608 + col * 9;
        const int g = gcol & 7, colpar = (gcol >> 3) & 1;
        const int nip = (gcol >> 4) & 3, wnGl = col >> 6;   // local wnG 0..7
        const int base = wnGl * 512 + nip * 128 + colpar * 2;
        #pragma unroll
        for (int t = 0; t < 4; t++) {
            stg[base + (g * 4 + t) * 4 + 0] =
                h2pack(cv0[2 * t + 1] * CSCALE, cv0[2 * t + 2] * CSCALE);
            stg[base + (g * 4 + t) * 4 + 1] =
                h2pack(cv1[2 * t + 1] * CSCALE, cv1[2 * t + 2] * CSCALE);
        }
        g_part[(size_t)ip * OUT_F + gcol] = cv0[0] + cv1[0];
    }
    __syncthreads();
    float4* dst = reinterpret_cast<float4*>(g_BF);
    const float4* src = reinterpret_cast<const float4*>(stg);
    #pragma unroll
    for (int k = 0; k < 4; k++) {
        const int q = threadIdx.x + (k << 8);          // 0..1023
        const int wnG = (h << 3) + (q >> 7), inner = q & 127;
        dst[(size_t)(c * 16 + wnG) * 512 + s * 128 + inner] = src[q];
    }
}

__global__ void __launch_bounds__(256) bias_red_kernel() {
    const int o = (blockIdx.x << 8) + threadIdx.x;
    float s0 = 0.f, s1 = 0.f, s2 = 0.f, s3 = 0.f;
    #pragma unroll 4
    for (int b = 0; b < 512; b += 4) {
        s0 += g_part[(size_t)(b + 0) * OUT_F + o];
        s1 += g_part[(size_t)(b + 1) * OUT_F + o];
        s2 += g_part[(size_t)(b + 2) * OUT_F + o];
        s3 += g_part[(size_t)(b + 3) * OUT_F + o];
    }
    g_bias[o] = (s0 + s1) + (s2 + s3);
}

// ---------------------------------------------------------------- producer
__device__ __forceinline__ void produce_chunk(int n, int ptid,
                                              const float* __restrict__ X,
                                              const float4* __restrict__ bsrc,
                                              uint32_t smA, uint32_t smB) {
    const int st   = n & 3;
    const int tile = n >> 7;
    const int kc   = n & 127;
    const int bmP  = (tile >> 2) << 7;
    const int bxP  = tile & 3;
    const uint32_t dstB = smB + (uint32_t)(st * B_BYTES);
    #pragma unroll
    for (int k = 0; k < 16; k++) {
        const int wng = k >> 2;
        const int inner = ptid + ((k & 3) << 7);
        cpa16(dstB + (uint32_t)(wng * 8192 + inner * 16),
              bsrc + (size_t)(kc * 16 + (bxP << 2) + wng) * 512 + inner);
    }
    cpa_commit();
    const uint32_t aDst = smA + (uint32_t)(st * A_BYTES);
    #pragma unroll
    for (int e = 0; e < 2; e++) {
        const int u = ptid + (e << 7);
        const int s_ = u & 3, g_ = (u >> 2) & 7, G_ = u >> 5;
        const int rA = bmP + (G_ << 4) + g_;
        const float2 xA = *reinterpret_cast<const float2*>(
            X + (size_t)rA * IN_F + (kc << 3) + (s_ << 1));
        const float2 xB = *reinterpret_cast<const float2*>(
            X + (size_t)(rA + 8) * IN_F + (kc << 3) + (s_ << 1));
        const float tA0 = fast_tanh(xA.x), tA1 = fast_tanh(xA.y);
        const float tB0 = fast_tanh(xB.x), tB1 = fast_tanh(xB.y);
        float TA0[8], TA1[8], TB0[8], TB1[8];
        TA0[0] = tA0; TA1[0] = tA1; TB0[0] = tB0; TB1[0] = tB1;
        TA0[1] = 2.f * tA0 * tA0 - 1.f;
        TA1[1] = 2.f * tA1 * tA1 - 1.f;
        TB0[1] = 2.f * tB0 * tB0 - 1.f;
        TB1[1] = 2.f * tB1 * tB1 - 1.f;
        #pragma unroll
        for (int d = 2; d < 8; d++) {
            TA0[d] = 2.f * tA0 * TA0[d - 1] - TA0[d - 2];
            TA1[d] = 2.f * tA1 * TA1[d - 1] - TA1[d - 2];
            TB0[d] = 2.f * tB0 * TB0[d - 1] - TB0[d - 2];
            TB1[d] = 2.f * tB1 * TB1[d - 1] - TB1[d - 2];
        }
        const uint32_t ab = aDst + (uint32_t)(s_ * 4096 + G_ * 512);
        #pragma unroll
        for (int t = 0; t < 4; t++)
            sts128(ab + a_lswz((uint32_t)(g_ * 4 + t)),
                   h2pack(TA0[2 * t], TA0[2 * t + 1]),
                   h2pack(TB0[2 * t], TB0[2 * t + 1]),
                   h2pack(TA1[2 * t], TA1[2 * t + 1]),
                   h2pack(TB1[2 * t], TB1[2 * t + 1]));
    }
}

// ---------------------------------------------------------------- main GEMM
__global__ void __launch_bounds__(NTHR, 1) cheby_main(const float* __restrict__ X,
                                                      float* __restrict__ Out) {
    extern __shared__ uint8_t sm[];
    __shared__ int s_last;
    const uint32_t smA = (uint32_t)__cvta_generic_to_shared(sm);          // 4 x 16KB
    const uint32_t smB = smA + NSTG * A_BYTES;                            // 4 x 32KB

    const int tid  = threadIdx.x;
    const int lane = tid & 31;
    const int w    = tid >> 5;
    const int p    = blockIdx.x;
    const int G    = gridDim.x;
    const int q0   = (int)(((long long)p * NTOT) / G);
    const int q1   = (int)(((long long)(p + 1) * NTOT) / G);

    const float4* bsrc = reinterpret_cast<const float4*>(g_BF);

    if (w < 8) {
        // ======================= CONSUMER (256 threads) =====================
        const int wm = w >> 2;
        const int wn = w & 3;
        const int g  = lane >> 2;
        const int t  = lane & 3;
        const uint32_t lsw = a_lswz((uint32_t)lane);

        int j = q0;
        while (j < q1) {
            const int tile = j >> 7;
            const int c0   = j & 127;
            const int rem  = q1 - j;
            const int cend = (c0 + rem < 128) ? (c0 + rem) : 128;

            float acc[4][8][4];
            #pragma unroll
            for (int mi = 0; mi < 4; mi++)
                #pragma unroll
                for (int ni = 0; ni < 8; ni++)
                    #pragma unroll
                    for (int q = 0; q < 4; q++) acc[mi][ni][q] = 0.f;

            for (int c = c0; c < cend; c++, j++) {
                const int st = j & 3;
                bar_sync_id(1 + st);
                const uint32_t aBase = smA + (uint32_t)(st * A_BYTES + wm * 2048) + lsw;
                const uint32_t bBase = smB + (uint32_t)(st * B_BYTES + wn * 8192 + lane * 16);
                #pragma unroll
                for (int s = 0; s < 4; s++) {
                    uint4 aC[4];
                    #pragma unroll
                    for (int mi = 0; mi < 4; mi++)
                        lds128(aC[mi], aBase + (uint32_t)(s * 4096 + mi * 512));
                    uint4 bC[4];
                    #pragma unroll
                    for (int nip = 0; nip < 4; nip++)
                        lds128(bC[nip], bBase + (uint32_t)(s * 2048 + nip * 512));
                    #pragma unroll
                    for (int ni = 0; ni < 8; ni++) {
                        const uint32_t b0 = (ni & 1) ? bC[ni >> 1].z : bC[ni >> 1].x;
                        const uint32_t b1 = (ni & 1) ? bC[ni >> 1].w : bC[ni >> 1].y;
                        #pragma unroll
                        for (int mi = 0; mi < 4; mi++)
                            mma16(acc[mi][ni], aC[mi], b0, b1);
                    }
                }
                bar_arrive_id(5 + st);
            }

            // ---- epilogue for this segment ----
            const int bm = (tile >> 2) << 7;
            const int bn = (tile & 3) << 8;
            if (c0 == 0 && cend == 128) {
                #pragma unroll
                for (int ni = 0; ni < 8; ni++) {
                    const int cc = bn + (wn << 6) + (ni << 3) + (t << 1);
                    const float2 bv = *reinterpret_cast<const float2*>(g_bias + cc);
                    #pragma unroll
                    for (int mi = 0; mi < 4; mi++) {
                        const int r0 = bm + (wm << 6) + (mi << 4) + g;
                        float2 o0 = { fmaf(acc[mi][ni][0], OSCALE, bv.x),
                                      fmaf(acc[mi][ni][1], OSCALE, bv.y) };
                        float2 o1 = { fmaf(acc[mi][ni][2], OSCALE, bv.x),
                                      fmaf(acc[mi][ni][3], OSCALE, bv.y) };
                        *reinterpret_cast<float2*>(Out + (size_t)r0 * OUT_F + cc)       = o0;
                        *reinterpret_cast<float2*>(Out + (size_t)(r0 + 8) * OUT_F + cc) = o1;
                    }
                }
            } else {
                const int half = (c0 == 0) ? 0 : 1;
                float* pt = g_Ps + ((size_t)tile * 2 + half) * 32768;
                #pragma unroll
                for (int ni = 0; ni < 8; ni++) {
                    const int ccl = (wn << 6) + (ni << 3) + (t << 1);
                    #pragma unroll
                    for (int mi = 0; mi < 4; mi++) {
                        const int r0 = (wm << 6) + (mi << 4) + g;
                        float2 o0 = { acc[mi][ni][0], acc[mi][ni][1] };
                        float2 o1 = { acc[mi][ni][2], acc[mi][ni][3] };
                        *reinterpret_cast<float2*>(pt + r0 * BN + ccl)       = o0;
                        *reinterpret_cast<float2*>(pt + (r0 + 8) * BN + ccl) = o1;
                    }
                }
                __threadfence();
                bar_sync_cons();
                if (tid == 0) s_last = (atomicAdd(&g_tk[tile], 1) == 1);
                bar_sync_cons();
                if (s_last) {
                    __threadfence();
                    const float4* p4 = reinterpret_cast<const float4*>(g_Ps);
                    const size_t bLo = ((size_t)tile * 2 + 0) * 8192;
                    const size_t bHi = ((size_t)tile * 2 + 1) * 8192;
                    #pragma unroll 4
                    for (int k = 0; k < 32; k++) {
                        const int q  = tid + (k << 8);
                        const int r  = q >> 6;
                        const int c4 = q & 63;
                        const float4 lo = p4[bLo + q];
                        const float4 hi = p4[bHi + q];
                        const float4 bv = *reinterpret_cast<const float4*>(
                            g_bias + bn + c4 * 4);
                        float4 o;
                        o.x = fmaf(lo.x + hi.x, OSCALE, bv.x);
                        o.y = fmaf(lo.y + hi.y, OSCALE, bv.y);
                        o.z = fmaf(lo.z + hi.z, OSCALE, bv.z);
                        o.w = fmaf(lo.w + hi.w, OSCALE, bv.w);
                        *reinterpret_cast<float4*>(
                            Out + (size_t)(bm + r) * OUT_F + bn + c4 * 4) = o;
                    }
                    if (tid == 0) g_tk[tile] = 0;
                }
            }
        }
    } else {
        // ======================= PRODUCER (128 threads) =====================
        const int ptid = tid - 256;
        produce_chunk(q0, ptid, X, bsrc, smA, smB);
        for (int n = q0 + 1; n < q1; n++) {
            if (n >= q0 + NSTG) bar_sync_id(5 + (n & 3));
            produce_chunk(n, ptid, X, bsrc, smA, smB);
            cpa_wait<1>();
            bar_arrive_id(1 + ((n - 1) & 3));
        }
        cpa_wait<0>();
        bar_arrive_id(1 + ((q1 - 1) & 3));
    }
}

// --------------------------------------------------------------------------
extern "C" void kernel_launch(void* const* d_in, const int* in_sizes, int n_in,
                              void* d_out, int out_size) {
    (void)in_sizes; (void)n_in; (void)out_size;
    const float* x    = (const float*)d_in[0];
    const float* coef = (const float*)d_in[1];
    float* out        = (float*)d_out;

    const int smem_bytes = NSTG * STAGE_BYTES;   // 196608
    cudaFuncSetAttribute(cheby_main, cudaFuncAttributeMaxDynamicSharedMemorySize,
                         smem_bytes);
    const int prep_smem = 9216 * 4 + 4096 * 4;   // 53248
    cudaFuncSetAttribute(prep_kernel, cudaFuncAttributeMaxDynamicSharedMemorySize,
                         prep_smem);

    int nsm = 148;
    cudaDeviceGetAttribute(&nsm, cudaDevAttrMultiProcessorCount, 0);
    if (nsm < 32 || nsm > 256) nsm = 148;

    prep_kernel<<<1024, 256, prep_smem>>>(coef);
    bias_red_kernel<<<4, 256>>>();
    cheby_main<<<nsm, NTHR, smem_bytes>>>(x, out);
}